// round 1
// baseline (speedup 1.0000x reference)
#include <cuda_runtime.h>
#include <math.h>

#define NN 100000
#define GG 100
#define NE 1000000
#define HH 256
#define TT 4

// ---------------- scratch (device globals; no allocation allowed) ----------
__device__ float d_h[(size_t)NN * HH];
__device__ float d_trans[(size_t)TT * NN * HH];
__device__ float d_msgs[(size_t)NN * HH];
__device__ float d_g1[(size_t)NN * 3 * HH];
__device__ float d_g2[(size_t)NN * 3 * HH];
__device__ float d_gate[NN];
__device__ float d_out2[NN * 2];
__device__ float d_partial[256];
__device__ float d_gmax;
__device__ int   d_cum[GG + 1];
__device__ float d_S[GG];
__device__ float d_P[GG * 2];

// ---------------- init: h = embed[tok] + positional encoding ---------------
__global__ void init_h_kernel(const int* __restrict__ nodes,
                              const float* __restrict__ embed) {
    int idx = blockIdx.x * blockDim.x + threadIdx.x;
    if (idx >= NN * HH) return;
    int n = idx >> 8;
    int i = idx & 255;
    int tok = nodes[n];
    int pos = nodes[NN + n];
    int p = pos < 512 ? pos : 512;
    float pe = 0.0f;
    if (p > 0) {
        float posf = (float)(p - 1);
        float div = powf(10000.0f, (2.0f * (float)i) / 256.0f);
        float ang = posf / div;
        pe = (i & 1) ? cosf(ang) : sinf(ang);
    }
    d_h[idx] = embed[tok * HH + i] + pe;
}

// ---------------- SGEMM: C(N x M) = A(N x 256) @ B(256 x M) + bias --------
// 128x128 tile, BK=16, 256 threads, 8x8 microtile (split 4+4 for bank-free LDS)
#define BM 128
#define BN 128
#define BK 16

__global__ __launch_bounds__(256)
void sgemm_bias(const float* __restrict__ A, const float* __restrict__ B,
                const float* __restrict__ bias, float* __restrict__ C,
                int nRows, int M) {
    const int K = 256;
    __shared__ float As[BK][BM + 4];
    __shared__ float Bs[BK][BN];

    int tid = threadIdx.x;
    int tx = tid & 15;
    int ty = tid >> 4;
    int rowBase = blockIdx.x * BM;
    int colBase = blockIdx.y * BN;

    float acc[8][8];
#pragma unroll
    for (int i = 0; i < 8; i++)
#pragma unroll
        for (int j = 0; j < 8; j++) acc[i][j] = 0.0f;

    int aRow = tid >> 2;          // 0..63
    int aK   = (tid & 3) * 4;     // 0,4,8,12
    int bRow = tid >> 5;          // 0..7
    int bCol = (tid & 31) * 4;    // 0..124

    for (int k0 = 0; k0 < K; k0 += BK) {
#pragma unroll
        for (int r = 0; r < 2; r++) {
            int row = rowBase + aRow + r * 64;
            float4 v = make_float4(0.f, 0.f, 0.f, 0.f);
            if (row < nRows)
                v = *(const float4*)(A + (size_t)row * K + k0 + aK);
            As[aK + 0][aRow + r * 64] = v.x;
            As[aK + 1][aRow + r * 64] = v.y;
            As[aK + 2][aRow + r * 64] = v.z;
            As[aK + 3][aRow + r * 64] = v.w;
        }
#pragma unroll
        for (int r = 0; r < 2; r++) {
            int kk = k0 + bRow + r * 8;
            *(float4*)&Bs[bRow + r * 8][bCol] =
                *(const float4*)(B + (size_t)kk * M + colBase + bCol);
        }
        __syncthreads();
#pragma unroll
        for (int k = 0; k < BK; k++) {
            float4 a0 = *(float4*)&As[k][ty * 4];
            float4 a1 = *(float4*)&As[k][64 + ty * 4];
            float4 b0 = *(float4*)&Bs[k][tx * 4];
            float4 b1 = *(float4*)&Bs[k][64 + tx * 4];
            float ra[8] = {a0.x, a0.y, a0.z, a0.w, a1.x, a1.y, a1.z, a1.w};
            float rb[8] = {b0.x, b0.y, b0.z, b0.w, b1.x, b1.y, b1.z, b1.w};
#pragma unroll
            for (int i = 0; i < 8; i++)
#pragma unroll
                for (int j = 0; j < 8; j++)
                    acc[i][j] = fmaf(ra[i], rb[j], acc[i][j]);
        }
        __syncthreads();
    }

    int c0 = colBase + tx * 4;
    float4 bj0 = *(const float4*)(bias + c0);
    float4 bj1 = *(const float4*)(bias + c0 + 64);
#pragma unroll
    for (int i = 0; i < 8; i++) {
        int row = rowBase + ((i < 4) ? (ty * 4 + i) : (64 + ty * 4 + (i - 4)));
        if (row >= nRows) continue;
        float4 o0 = make_float4(acc[i][0] + bj0.x, acc[i][1] + bj0.y,
                                acc[i][2] + bj0.z, acc[i][3] + bj0.w);
        float4 o1 = make_float4(acc[i][4] + bj1.x, acc[i][5] + bj1.y,
                                acc[i][6] + bj1.z, acc[i][7] + bj1.w);
        *(float4*)(C + (size_t)row * M + c0)      = o0;
        *(float4*)(C + (size_t)row * M + c0 + 64) = o1;
    }
}

// ---------------- zero a float buffer (float4) -----------------------------
__global__ void zero_kernel(float* __restrict__ p, int n4) {
    int i = blockIdx.x * blockDim.x + threadIdx.x;
    if (i < n4) ((float4*)p)[i] = make_float4(0.f, 0.f, 0.f, 0.f);
}

// ---------------- edge scatter: msgs[tgt] += trans[etype][src] -------------
__global__ void scatter_kernel(const int* __restrict__ edges) {
    int idx = blockIdx.x * blockDim.x + threadIdx.x;
    int e = idx >> 6;
    if (e >= NE) return;
    int lane = idx & 63;
    int et  = edges[e * 3 + 0];
    int src = edges[e * 3 + 1];
    int tgt = edges[e * 3 + 2];
    const float4 v =
        *(const float4*)&d_trans[((size_t)et * NN + src) * HH + lane * 4];
    float* dst = &d_msgs[(size_t)tgt * HH + lane * 4];
    asm volatile("red.global.add.v4.f32 [%0], {%1,%2,%3,%4};"
                 :: "l"(dst), "f"(v.x), "f"(v.y), "f"(v.z), "f"(v.w)
                 : "memory");
}

// ---------------- GRU pointwise update -------------------------------------
__device__ __forceinline__ float sigm(float x) { return 1.0f / (1.0f + expf(-x)); }

__global__ void gru_kernel() {
    int idx = blockIdx.x * blockDim.x + threadIdx.x;
    if (idx >= NN * 64) return;
    int n = idx >> 6;
    int c = (idx & 63) * 4;
    size_t b = (size_t)n * 768;
    float4 xz = *(float4*)&d_g1[b + c];
    float4 xr = *(float4*)&d_g1[b + 256 + c];
    float4 xh = *(float4*)&d_g1[b + 512 + c];
    float4 hz = *(float4*)&d_g2[b + c];
    float4 hr = *(float4*)&d_g2[b + 256 + c];
    float4 hh = *(float4*)&d_g2[b + 512 + c];
    float4 ho = *(float4*)&d_h[(size_t)n * 256 + c];
    float4 o;
#define GRU1(comp)                                                     \
    {                                                                  \
        float z = sigm(xz.comp + hz.comp);                             \
        float r = sigm(xr.comp + hr.comp);                             \
        float cand = tanhf(xh.comp + r * hh.comp);                     \
        o.comp = z * ho.comp + (1.0f - z) * cand;                      \
    }
    GRU1(x) GRU1(y) GRU1(z) GRU1(w)
#undef GRU1
    *(float4*)&d_h[(size_t)n * 256 + c] = o;
}

// ---------------- readout head: gate logits + out2 (warp per node) ---------
__global__ void head_kernel(const float* __restrict__ gateW,
                            const float* __restrict__ gateb,
                            const float* __restrict__ outW,
                            const float* __restrict__ outb) {
    int gidx = blockIdx.x * blockDim.x + threadIdx.x;
    int warp = gidx >> 5;
    int lane = gidx & 31;
    if (warp >= NN) return;
    float g = 0.f, o0 = 0.f, o1 = 0.f;
    for (int c = lane; c < HH; c += 32) {
        float hv = d_h[(size_t)warp * HH + c];
        g  += hv * gateW[c];
        o0 += hv * outW[c * 2 + 0];
        o1 += hv * outW[c * 2 + 1];
    }
#pragma unroll
    for (int off = 16; off; off >>= 1) {
        g  += __shfl_down_sync(0xffffffffu, g,  off);
        o0 += __shfl_down_sync(0xffffffffu, o0, off);
        o1 += __shfl_down_sync(0xffffffffu, o1, off);
    }
    if (lane == 0) {
        d_gate[warp] = g + gateb[0];
        d_out2[warp * 2 + 0] = o0 + outb[0];
        d_out2[warp * 2 + 1] = o1 + outb[1];
    }
}

// ---------------- global max of gate logits --------------------------------
__global__ void max1_kernel() {
    __shared__ float s[256];
    float m = -INFINITY;
    for (int i = blockIdx.x * 256 + threadIdx.x; i < NN; i += gridDim.x * 256)
        m = fmaxf(m, d_gate[i]);
    s[threadIdx.x] = m;
    __syncthreads();
    for (int o = 128; o; o >>= 1) {
        if (threadIdx.x < o) s[threadIdx.x] = fmaxf(s[threadIdx.x], s[threadIdx.x + o]);
        __syncthreads();
    }
    if (threadIdx.x == 0) d_partial[blockIdx.x] = s[0];
}

__global__ void max2_kernel(int nb) {
    __shared__ float s[256];
    float m = (threadIdx.x < nb) ? d_partial[threadIdx.x] : -INFINITY;
    s[threadIdx.x] = m;
    __syncthreads();
    for (int o = 128; o; o >>= 1) {
        if (threadIdx.x < o) s[threadIdx.x] = fmaxf(s[threadIdx.x], s[threadIdx.x + o]);
        __syncthreads();
    }
    if (threadIdx.x == 0) d_gmax = s[0];
}

// ---------------- segment offsets + per-graph accumulation -----------------
__global__ void cum_kernel(const int* __restrict__ gs) {
    if (threadIdx.x == 0 && blockIdx.x == 0) {
        int c = 0;
        d_cum[0] = 0;
        for (int i = 0; i < GG; i++) { c += gs[i]; d_cum[i + 1] = c; }
    }
}

__global__ void zero_sp_kernel() {
    int i = threadIdx.x;
    if (i < GG) d_S[i] = 0.f;
    if (i < GG * 2) d_P[i] = 0.f;
}

__global__ void accum_kernel() {
    int n = blockIdx.x * blockDim.x + threadIdx.x;
    if (n >= NN) return;
    int lo = 0, hi = GG;  // largest g with cum[g] <= n
    while (hi - lo > 1) {
        int mid = (lo + hi) >> 1;
        if (d_cum[mid] <= n) lo = mid; else hi = mid;
    }
    int seg = lo;
    float e = expf(d_gate[n] - d_gmax);
    atomicAdd(&d_S[seg], e);
    atomicAdd(&d_P[seg * 2 + 0], e * d_out2[n * 2 + 0]);
    atomicAdd(&d_P[seg * 2 + 1], e * d_out2[n * 2 + 1]);
}

__global__ void final_kernel(float* __restrict__ out) {
    int i = threadIdx.x;
    if (i < GG * 2) out[i] = d_P[i] / (d_S[i >> 1] + 1e-16f);
}

// ---------------- host orchestration ---------------------------------------
extern "C" void kernel_launch(void* const* d_in, const int* in_sizes, int n_in,
                              void* d_out, int out_size) {
    const int*   nodes       = (const int*)d_in[0];
    const int*   graph_sizes = (const int*)d_in[1];
    const int*   edges       = (const int*)d_in[2];
    const float* embed       = (const float*)d_in[3];
    const float* tw          = (const float*)d_in[4];
    const float* tb          = (const float*)d_in[5];
    const float* gruW        = (const float*)d_in[6];
    const float* gruU        = (const float*)d_in[7];
    const float* gbi         = (const float*)d_in[8];
    const float* gbr         = (const float*)d_in[9];
    const float* gateW       = (const float*)d_in[10];
    const float* gateb       = (const float*)d_in[11];
    const float* outW        = (const float*)d_in[12];
    const float* outb        = (const float*)d_in[13];
    float* out = (float*)d_out;

    float *p_h, *p_trans, *p_msgs, *p_g1, *p_g2;
    cudaGetSymbolAddress((void**)&p_h, d_h);
    cudaGetSymbolAddress((void**)&p_trans, d_trans);
    cudaGetSymbolAddress((void**)&p_msgs, d_msgs);
    cudaGetSymbolAddress((void**)&p_g1, d_g1);
    cudaGetSymbolAddress((void**)&p_g2, d_g2);

    init_h_kernel<<<(NN * HH + 255) / 256, 256>>>(nodes, embed);

    const int layers[4] = {0, 0, 0, 1};
    dim3 gridT((NN + BM - 1) / BM, 2);    // M = 256
    dim3 gridG((NN + BM - 1) / BM, 6);    // M = 768

    for (int s = 0; s < 4; s++) {
        int l = layers[s];
        for (int t = 0; t < TT; t++) {
            sgemm_bias<<<gridT, 256>>>(
                p_h,
                tw + ((size_t)(l * TT + t)) * HH * HH,
                tb + (size_t)(l * TT + t) * HH,
                p_trans + (size_t)t * NN * HH,
                NN, HH);
        }
        zero_kernel<<<(NN * HH / 4 + 255) / 256, 256>>>(p_msgs, NN * HH / 4);
        scatter_kernel<<<(size_t)NE * 64 / 256, 256>>>(edges);
        sgemm_bias<<<gridG, 256>>>(p_msgs, gruW + (size_t)l * HH * 768,
                                   gbi + (size_t)l * 768, p_g1, NN, 768);
        sgemm_bias<<<gridG, 256>>>(p_h, gruU + (size_t)l * HH * 768,
                                   gbr + (size_t)l * 768, p_g2, NN, 768);
        gru_kernel<<<(NN * 64 + 255) / 256, 256>>>();
    }

    head_kernel<<<(NN * 32 + 255) / 256, 256>>>(gateW, gateb, outW, outb);
    max1_kernel<<<256, 256>>>();
    max2_kernel<<<1, 256>>>(256);
    cum_kernel<<<1, 1>>>(graph_sizes);
    zero_sp_kernel<<<1, 256>>>();
    accum_kernel<<<(NN + 255) / 256, 256>>>();
    final_kernel<<<1, 256>>>(out);
}

// round 3
// speedup vs baseline: 1.2360x; 1.2360x over previous
#include <cuda_runtime.h>
#include <cstdint>
#include <math.h>
#include <mma.h>

using namespace nvcuda;

#define NN 100000
#define NN_PAD 100096
#define GG 100
#define NE 1000000
#define HH 256
#define TT 4

__device__ __forceinline__ float rna_tf32(float x) {
    float o;
    asm("cvt.rna.tf32.f32 %0, %1;" : "=f"(o) : "f"(x));
    return o;
}
__device__ __forceinline__ uint32_t smem_u32(const void* p) {
    uint32_t a;
    asm("{ .reg .u64 t; cvta.to.shared.u64 t, %1; cvt.u32.u64 %0, t; }"
        : "=r"(a) : "l"(p));
    return a;
}

// ===================== scratch (device globals) =============================
__device__ float d_h[(size_t)NN * HH];
__device__ float d_trans[(size_t)NN_PAD * TT * HH];   // [node][t][256]
__device__ float d_msgs[(size_t)NN * HH];
__device__ float d_g1[(size_t)NN_PAD * 3 * HH];
__device__ float d_g2[(size_t)NN_PAD * 3 * HH];
__device__ float d_twT[(size_t)2 * 1024 * 256];       // [l][n=1024][k]
__device__ float d_WT[(size_t)2 * 768 * 256];         // [l][n=768][k]
__device__ float d_UT[(size_t)2 * 768 * 256];
__device__ float d_gate[NN];
__device__ float d_out2[NN * 2];
__device__ float d_partial[256];
__device__ float d_gmax;
__device__ int   d_cum[GG + 1];
__device__ float d_S[GG];
__device__ float d_P[GG * 2];

// ===================== weight prep (transpose + tf32 round) =================
__global__ void prep_tw_kernel(const float* __restrict__ tw) {
    int o = blockIdx.x * blockDim.x + threadIdx.x;
    if (o >= 2 * 1024 * 256) return;
    int l = o >> 18;
    int n = (o >> 8) & 1023;
    int k = o & 255;
    int t = n >> 8, j = n & 255;
    d_twT[o] = rna_tf32(tw[((size_t)(l * 4 + t) * 256 + k) * 256 + j]);
}
__global__ void prep_gru_kernel(const float* __restrict__ W,
                                const float* __restrict__ U) {
    int o = blockIdx.x * blockDim.x + threadIdx.x;
    if (o >= 2 * 768 * 256) return;
    int l = o / (768 * 256);
    int n = (o >> 8) % 768;
    int k = o & 255;
    size_t in = ((size_t)l * 256 + k) * 768 + n;
    d_WT[o] = rna_tf32(W[in]);
    d_UT[o] = rna_tf32(U[in]);
}

// ===================== init h ===============================================
__global__ void init_h_kernel(const int* __restrict__ nodes,
                              const float* __restrict__ embed) {
    int idx = blockIdx.x * blockDim.x + threadIdx.x;
    if (idx >= NN * HH) return;
    int n = idx >> 8;
    int i = idx & 255;
    int tok = nodes[n];
    int pos = nodes[NN + n];
    int p = pos < 512 ? pos : 512;
    float pe = 0.0f;
    if (p > 0) {
        float posf = (float)(p - 1);
        float div = powf(10000.0f, (2.0f * (float)i) / 256.0f);
        float ang = posf / div;
        pe = (i & 1) ? cosf(ang) : sinf(ang);
    }
    d_h[idx] = embed[tok * HH + i] + pe;
}

// ===================== tf32 WMMA GEMM =======================================
// C[*, ldC] tile(128x128) = A[NN,256] @ BT^T + bias; BT is [ldC,256] K-major.
// 256 threads = 8 warps in 4x2 grid, warp tile 32x64. BK=32, double-buffered.
#define LDS_T 36           // padded smem leading dim (floats)
#define TBUF (128 * LDS_T) // one buffer (floats)
#define GEMM_SMEM_BYTES ((4 * TBUF + 16 * 128) * 4)

__global__ __launch_bounds__(256, 2)
void gemm_wmma(const float* __restrict__ A, const float* __restrict__ BT,
               const float* __restrict__ bias, float* __restrict__ C,
               int ldC) {
    extern __shared__ float sm[];
    float* sA = sm;                 // [2][128*LDS_T] row-major
    float* sB = sm + 2 * TBUF;      // [2][128*LDS_T] col-major (per out-col)
    float* sBias = sm + 4 * TBUF;   // [16*128]

    const int tid = threadIdx.x;
    const int wid = tid >> 5;
    const int wr = wid & 3;         // warp row 0..3  -> rows wr*32
    const int wc = wid >> 2;        // warp col 0..1  -> cols wc*64
    const int mBase = blockIdx.x * 128;
    const int colBase = blockIdx.y * 128;
    const uint32_t sBu = smem_u32(sB);

    // bias stage (16 identical rows)
    for (int i = tid; i < 16 * 128; i += 256)
        sBias[i] = bias[colBase + (i & 127)];

    float4 ar[4];
    int fi0 = tid * 4;

    // --- helpers -----------------------------------------------------------
#define CP_B(c, buf)                                                          \
    {                                                                         \
        _Pragma("unroll")                                                     \
        for (int r = 0; r < 4; r++) {                                         \
            int fi = fi0 + r;                                                 \
            int col = fi >> 3, q = fi & 7;                                    \
            uint32_t dst = sBu + (uint32_t)(((buf) * TBUF + col * LDS_T + q * 4) * 4); \
            const float* src = BT + (size_t)(colBase + col) * 256 + (c) * 32 + q * 4;  \
            asm volatile("cp.async.cg.shared.global [%0], [%1], 16;"          \
                         :: "r"(dst), "l"(src));                              \
        }                                                                     \
        asm volatile("cp.async.commit_group;" ::: "memory");                  \
    }
#define LD_A(c)                                                               \
    {                                                                         \
        _Pragma("unroll")                                                     \
        for (int r = 0; r < 4; r++) {                                         \
            int fi = fi0 + r;                                                 \
            int row = fi >> 3, q = fi & 7;                                    \
            int gr = mBase + row;                                             \
            ar[r] = (gr < NN) ? *(const float4*)(A + (size_t)gr * 256 + (c) * 32 + q * 4) \
                              : make_float4(0.f, 0.f, 0.f, 0.f);              \
        }                                                                     \
    }
#define ST_A(buf)                                                             \
    {                                                                         \
        _Pragma("unroll")                                                     \
        for (int r = 0; r < 4; r++) {                                         \
            int fi = fi0 + r;                                                 \
            int row = fi >> 3, q = fi & 7;                                    \
            float4 v = ar[r];                                                 \
            v.x = rna_tf32(v.x); v.y = rna_tf32(v.y);                         \
            v.z = rna_tf32(v.z); v.w = rna_tf32(v.w);                         \
            *(float4*)(sA + (buf) * TBUF + row * LDS_T + q * 4) = v;          \
        }                                                                     \
    }
    // -----------------------------------------------------------------------

    CP_B(0, 0);
    LD_A(0);
    ST_A(0);
    __syncthreads();

    wmma::fragment<wmma::accumulator, 16, 16, 8, float> acc[2][4];
#pragma unroll
    for (int i = 0; i < 2; i++)
#pragma unroll
        for (int j = 0; j < 4; j++)
            wmma::load_matrix_sync(acc[i][j], sBias + wc * 64 + j * 16, 128,
                                   wmma::mem_row_major);

    int cur = 0;
#pragma unroll 1
    for (int c = 0; c < 8; c++) {
        if (c < 7) {
            CP_B(c + 1, cur ^ 1);
            LD_A(c + 1);
            asm volatile("cp.async.wait_group 1;" ::: "memory");
        } else {
            asm volatile("cp.async.wait_group 0;" ::: "memory");
        }
        __syncthreads();

        const float* aBase = sA + cur * TBUF;
        const float* bBase = sB + cur * TBUF;
#pragma unroll
        for (int k8 = 0; k8 < 4; k8++) {
            wmma::fragment<wmma::matrix_a, 16, 16, 8, wmma::precision::tf32,
                           wmma::row_major> fa[2];
            wmma::fragment<wmma::matrix_b, 16, 16, 8, wmma::precision::tf32,
                           wmma::col_major> fb[4];
#pragma unroll
            for (int i = 0; i < 2; i++)
                wmma::load_matrix_sync(fa[i],
                    aBase + (wr * 32 + i * 16) * LDS_T + k8 * 8, LDS_T);
#pragma unroll
            for (int j = 0; j < 4; j++)
                wmma::load_matrix_sync(fb[j],
                    bBase + (wc * 64 + j * 16) * LDS_T + k8 * 8, LDS_T);
#pragma unroll
            for (int i = 0; i < 2; i++)
#pragma unroll
                for (int j = 0; j < 4; j++)
                    wmma::mma_sync(acc[i][j], fa[i], fb[j], acc[i][j]);
        }
        __syncthreads();
        if (c < 7) {
            ST_A(cur ^ 1);
            cur ^= 1;
        }
    }

    // epilogue: direct store (C buffers are row-padded, no guard needed)
#pragma unroll
    for (int i = 0; i < 2; i++)
#pragma unroll
        for (int j = 0; j < 4; j++)
            wmma::store_matrix_sync(
                C + (size_t)(mBase + wr * 32 + i * 16) * ldC + colBase +
                    wc * 64 + j * 16,
                acc[i][j], ldC, wmma::mem_row_major);
#undef CP_B
#undef LD_A
#undef ST_A
}

// ===================== zero / scatter / gru ================================
__global__ void zero_kernel(float* __restrict__ p, int n4) {
    int i = blockIdx.x * blockDim.x + threadIdx.x;
    if (i < n4) ((float4*)p)[i] = make_float4(0.f, 0.f, 0.f, 0.f);
}

__global__ void scatter_kernel(const int* __restrict__ edges) {
    int idx = blockIdx.x * blockDim.x + threadIdx.x;
    int e = idx >> 6;
    if (e >= NE) return;
    int lane = idx & 63;
    int et  = edges[e * 3 + 0];
    int src = edges[e * 3 + 1];
    int tgt = edges[e * 3 + 2];
    const float4 v =
        *(const float4*)&d_trans[((size_t)src * 4 + et) * HH + lane * 4];
    float* dst = &d_msgs[(size_t)tgt * HH + lane * 4];
    asm volatile("red.global.add.v4.f32 [%0], {%1,%2,%3,%4};"
                 :: "l"(dst), "f"(v.x), "f"(v.y), "f"(v.z), "f"(v.w)
                 : "memory");
}

__device__ __forceinline__ float sigm(float x) { return 1.0f / (1.0f + expf(-x)); }

__global__ void gru_kernel() {
    int idx = blockIdx.x * blockDim.x + threadIdx.x;
    if (idx >= NN * 64) return;
    int n = idx >> 6;
    int c = (idx & 63) * 4;
    size_t b = (size_t)n * 768;
    float4 xz = *(float4*)&d_g1[b + c];
    float4 xr = *(float4*)&d_g1[b + 256 + c];
    float4 xh = *(float4*)&d_g1[b + 512 + c];
    float4 hz = *(float4*)&d_g2[b + c];
    float4 hr = *(float4*)&d_g2[b + 256 + c];
    float4 hh = *(float4*)&d_g2[b + 512 + c];
    float4 ho = *(float4*)&d_h[(size_t)n * 256 + c];
    float4 o;
#define GRU1(comp)                                                     \
    {                                                                  \
        float z = sigm(xz.comp + hz.comp);                             \
        float r = sigm(xr.comp + hr.comp);                             \
        float cand = tanhf(xh.comp + r * hh.comp);                     \
        o.comp = z * ho.comp + (1.0f - z) * cand;                      \
    }
    GRU1(x) GRU1(y) GRU1(z) GRU1(w)
#undef GRU1
    *(float4*)&d_h[(size_t)n * 256 + c] = o;
}

// ===================== readout ==============================================
__global__ void head_kernel(const float* __restrict__ gateW,
                            const float* __restrict__ gateb,
                            const float* __restrict__ outW,
                            const float* __restrict__ outb) {
    int gidx = blockIdx.x * blockDim.x + threadIdx.x;
    int warp = gidx >> 5;
    int lane = gidx & 31;
    if (warp >= NN) return;
    float g = 0.f, o0 = 0.f, o1 = 0.f;
    for (int c = lane; c < HH; c += 32) {
        float hv = d_h[(size_t)warp * HH + c];
        g  += hv * gateW[c];
        o0 += hv * outW[c * 2 + 0];
        o1 += hv * outW[c * 2 + 1];
    }
#pragma unroll
    for (int off = 16; off; off >>= 1) {
        g  += __shfl_down_sync(0xffffffffu, g,  off);
        o0 += __shfl_down_sync(0xffffffffu, o0, off);
        o1 += __shfl_down_sync(0xffffffffu, o1, off);
    }
    if (lane == 0) {
        d_gate[warp] = g + gateb[0];
        d_out2[warp * 2 + 0] = o0 + outb[0];
        d_out2[warp * 2 + 1] = o1 + outb[1];
    }
}

__global__ void max1_kernel() {
    __shared__ float s[256];
    float m = -INFINITY;
    for (int i = blockIdx.x * 256 + threadIdx.x; i < NN; i += gridDim.x * 256)
        m = fmaxf(m, d_gate[i]);
    s[threadIdx.x] = m;
    __syncthreads();
    for (int o = 128; o; o >>= 1) {
        if (threadIdx.x < o) s[threadIdx.x] = fmaxf(s[threadIdx.x], s[threadIdx.x + o]);
        __syncthreads();
    }
    if (threadIdx.x == 0) d_partial[blockIdx.x] = s[0];
}

__global__ void max2_kernel(int nb) {
    __shared__ float s[256];
    float m = (threadIdx.x < nb) ? d_partial[threadIdx.x] : -INFINITY;
    s[threadIdx.x] = m;
    __syncthreads();
    for (int o = 128; o; o >>= 1) {
        if (threadIdx.x < o) s[threadIdx.x] = fmaxf(s[threadIdx.x], s[threadIdx.x + o]);
        __syncthreads();
    }
    if (threadIdx.x == 0) d_gmax = s[0];
}

__global__ void cum_kernel(const int* __restrict__ gs) {
    if (threadIdx.x == 0 && blockIdx.x == 0) {
        int c = 0;
        d_cum[0] = 0;
        for (int i = 0; i < GG; i++) { c += gs[i]; d_cum[i + 1] = c; }
    }
}

__global__ void zero_sp_kernel() {
    int i = threadIdx.x;
    if (i < GG) d_S[i] = 0.f;
    if (i < GG * 2) d_P[i] = 0.f;
}

__global__ void accum_kernel() {
    int n = blockIdx.x * blockDim.x + threadIdx.x;
    if (n >= NN) return;
    int lo = 0, hi = GG;
    while (hi - lo > 1) {
        int mid = (lo + hi) >> 1;
        if (d_cum[mid] <= n) lo = mid; else hi = mid;
    }
    int seg = lo;
    float e = expf(d_gate[n] - d_gmax);
    atomicAdd(&d_S[seg], e);
    atomicAdd(&d_P[seg * 2 + 0], e * d_out2[n * 2 + 0]);
    atomicAdd(&d_P[seg * 2 + 1], e * d_out2[n * 2 + 1]);
}

__global__ void final_kernel(float* __restrict__ out) {
    int i = threadIdx.x;
    if (i < GG * 2) out[i] = d_P[i] / (d_S[i >> 1] + 1e-16f);
}

// ===================== host orchestration ===================================
extern "C" void kernel_launch(void* const* d_in, const int* in_sizes, int n_in,
                              void* d_out, int out_size) {
    const int*   nodes       = (const int*)d_in[0];
    const int*   graph_sizes = (const int*)d_in[1];
    const int*   edges       = (const int*)d_in[2];
    const float* embed       = (const float*)d_in[3];
    const float* tw          = (const float*)d_in[4];
    const float* tb          = (const float*)d_in[5];
    const float* gruW        = (const float*)d_in[6];
    const float* gruU        = (const float*)d_in[7];
    const float* gbi         = (const float*)d_in[8];
    const float* gbr         = (const float*)d_in[9];
    const float* gateW       = (const float*)d_in[10];
    const float* gateb       = (const float*)d_in[11];
    const float* outW        = (const float*)d_in[12];
    const float* outb        = (const float*)d_in[13];
    float* out = (float*)d_out;

    float *p_h, *p_trans, *p_msgs, *p_g1, *p_g2, *p_twT, *p_WT, *p_UT;
    cudaGetSymbolAddress((void**)&p_h, d_h);
    cudaGetSymbolAddress((void**)&p_trans, d_trans);
    cudaGetSymbolAddress((void**)&p_msgs, d_msgs);
    cudaGetSymbolAddress((void**)&p_g1, d_g1);
    cudaGetSymbolAddress((void**)&p_g2, d_g2);
    cudaGetSymbolAddress((void**)&p_twT, d_twT);
    cudaGetSymbolAddress((void**)&p_WT, d_WT);
    cudaGetSymbolAddress((void**)&p_UT, d_UT);

    cudaFuncSetAttribute(gemm_wmma, cudaFuncAttributeMaxDynamicSharedMemorySize,
                         GEMM_SMEM_BYTES);

    prep_tw_kernel<<<(2 * 1024 * 256 + 255) / 256, 256>>>(tw);
    prep_gru_kernel<<<(2 * 768 * 256 + 255) / 256, 256>>>(gruW, gruU);
    init_h_kernel<<<(NN * HH + 255) / 256, 256>>>(nodes, embed);

    const int layers[4] = {0, 0, 0, 1};
    const int gridM = (NN + 127) / 128;          // 782
    dim3 gridT(gridM, 8);                         // N = 1024
    dim3 gridG(gridM, 6);                         // N = 768

    for (int s = 0; s < 4; s++) {
        int l = layers[s];
        gemm_wmma<<<gridT, 256, GEMM_SMEM_BYTES>>>(
            p_h, p_twT + (size_t)l * 1024 * 256, tb + (size_t)l * 1024,
            p_trans, 1024);
        zero_kernel<<<(NN * HH / 4 + 255) / 256, 256>>>(p_msgs, NN * HH / 4);
        scatter_kernel<<<(size_t)NE * 64 / 256, 256>>>(edges);
        gemm_wmma<<<gridG, 256, GEMM_SMEM_BYTES>>>(
            p_msgs, p_WT + (size_t)l * 768 * 256, gbi + (size_t)l * 768,
            p_g1, 768);
        gemm_wmma<<<gridG, 256, GEMM_SMEM_BYTES>>>(
            p_h, p_UT + (size_t)l * 768 * 256, gbr + (size_t)l * 768,
            p_g2, 768);
        gru_kernel<<<(NN * 64 + 255) / 256, 256>>>();
    }

    head_kernel<<<(NN * 32 + 255) / 256, 256>>>(gateW, gateb, outW, outb);
    max1_kernel<<<256, 256>>>();
    max2_kernel<<<1, 256>>>(256);
    cum_kernel<<<1, 1>>>(graph_sizes);
    zero_sp_kernel<<<1, 256>>>();
    accum_kernel<<<(NN + 255) / 256, 256>>>();
    final_kernel<<<1, 256>>>(out);
}

// round 4
// speedup vs baseline: 2.7809x; 2.2499x over previous
#include <cuda_runtime.h>
#include <cuda_fp16.h>
#include <cstdint>
#include <math.h>

#define NN 100000
#define NN_PAD 100096
#define MT16 (NN_PAD / 16)        // 6256 m16 tiles
#define GG 100
#define NE 1000000
#define HH 256
#define TT 4
#define J2H 112                   // 1792/16 n8-tile-pairs for fused h GEMM
#define J2M 48                    // 768/16 for msgs GEMM

// ===================== scratch (device globals) =============================
__device__ float d_h[(size_t)NN * HH];
__device__ float d_trans[(size_t)NN_PAD * TT * HH];   // [node][t][256] fp32
__device__ float d_msgs[(size_t)NN * HH];
__device__ float d_g1[(size_t)NN_PAD * 3 * HH];
__device__ float d_g2[(size_t)NN_PAD * 3 * HH];
__device__ uint4 d_hp[(size_t)MT16 * 512];            // permuted fp16 A (h)
__device__ uint4 d_msgsp[(size_t)MT16 * 512];         // permuted fp16 A (msgs)
__device__ uint4 d_BH[(size_t)2 * 16 * J2H * 32];     // permuted fp16 B (tw|U)
__device__ uint4 d_BM[(size_t)2 * 16 * J2M * 32];     // permuted fp16 B (W)
__device__ float d_biasH[2 * 1792];
__device__ float d_gate[NN];
__device__ float d_out2[NN * 2];
__device__ float d_partial[256];
__device__ float d_gmax;
__device__ int   d_cum[GG + 1];
__device__ float d_S[GG];
__device__ float d_P[GG * 2];

__device__ __forceinline__ uint32_t packh2(float lo, float hi) {
    __half2 h = __floats2half2_rn(lo, hi);   // .x = lo (low 16 bits)
    return *reinterpret_cast<uint32_t*>(&h);
}

// ===================== weight prep: fragment-layout fp16 ====================
// B[k][n] column n of fused weights; b0 halves (k0,k0+1), b1 (k0+8,k0+9)
__device__ __forceinline__ float bvalH(const float* tw, const float* U,
                                       int l, int k, int n) {
    if (n < 1024) return tw[((size_t)(l * 4 + (n >> 8)) * 256 + k) * 256 + (n & 255)];
    return U[((size_t)l * 256 + k) * 768 + (n - 1024)];
}

__global__ void prep_BH_kernel(const float* __restrict__ tw,
                               const float* __restrict__ U) {
    int t = blockIdx.x * blockDim.x + threadIdx.x;
    if (t >= 2 * 16 * J2H * 32) return;
    int lane = t & 31;
    int t2 = t >> 5;
    int j2 = t2 % J2H;
    int t3 = t2 / J2H;
    int kk = t3 & 15;
    int l  = t3 >> 4;
    int g = lane >> 2, tt = lane & 3;
    int k0 = kk * 16 + tt * 2;
    uint4 o;
    {
        int n = (j2 * 2 + 0) * 8 + g;
        o.x = packh2(bvalH(tw, U, l, k0, n),     bvalH(tw, U, l, k0 + 1, n));
        o.y = packh2(bvalH(tw, U, l, k0 + 8, n), bvalH(tw, U, l, k0 + 9, n));
    }
    {
        int n = (j2 * 2 + 1) * 8 + g;
        o.z = packh2(bvalH(tw, U, l, k0, n),     bvalH(tw, U, l, k0 + 1, n));
        o.w = packh2(bvalH(tw, U, l, k0 + 8, n), bvalH(tw, U, l, k0 + 9, n));
    }
    d_BH[t] = o;
}

__global__ void prep_BM_kernel(const float* __restrict__ W) {
    int t = blockIdx.x * blockDim.x + threadIdx.x;
    if (t >= 2 * 16 * J2M * 32) return;
    int lane = t & 31;
    int t2 = t >> 5;
    int j2 = t2 % J2M;
    int t3 = t2 / J2M;
    int kk = t3 & 15;
    int l  = t3 >> 4;
    int g = lane >> 2, tt = lane & 3;
    int k0 = kk * 16 + tt * 2;
    const float* Wl = W + (size_t)l * 256 * 768;
    uint4 o;
    {
        int n = (j2 * 2 + 0) * 8 + g;
        o.x = packh2(Wl[(size_t)k0 * 768 + n],       Wl[(size_t)(k0 + 1) * 768 + n]);
        o.y = packh2(Wl[(size_t)(k0 + 8) * 768 + n], Wl[(size_t)(k0 + 9) * 768 + n]);
    }
    {
        int n = (j2 * 2 + 1) * 8 + g;
        o.z = packh2(Wl[(size_t)k0 * 768 + n],       Wl[(size_t)(k0 + 1) * 768 + n]);
        o.w = packh2(Wl[(size_t)(k0 + 8) * 768 + n], Wl[(size_t)(k0 + 9) * 768 + n]);
    }
    d_BM[t] = o;
}

__global__ void prep_biasH_kernel(const float* __restrict__ tb,
                                  const float* __restrict__ gbr) {
    int t = blockIdx.x * blockDim.x + threadIdx.x;
    if (t >= 2 * 1792) return;
    int l = t / 1792, n = t % 1792;
    d_biasH[t] = (n < 1024) ? tb[l * 1024 + n] : gbr[l * 768 + (n - 1024)];
}

// ===================== activation permute: fp32 -> fragment fp16 ============
__global__ void permute_a_kernel(const float* __restrict__ A,
                                 uint4* __restrict__ Ap) {
    int t = blockIdx.x * blockDim.x + threadIdx.x;
    if (t >= MT16 * 512) return;
    int lane = t & 31;
    int kk = (t >> 5) & 15;
    int i  = t >> 9;
    int r = lane >> 2, c2 = (lane & 3) * 2;
    int row0 = i * 16 + r, row1 = row0 + 8;
    int col0 = kk * 16 + c2;
    float2 v00 = make_float2(0.f, 0.f), v01 = v00, v10 = v00, v11 = v00;
    if (row0 < NN) {
        v00 = *(const float2*)(A + (size_t)row0 * 256 + col0);
        v01 = *(const float2*)(A + (size_t)row0 * 256 + col0 + 8);
    }
    if (row1 < NN) {
        v10 = *(const float2*)(A + (size_t)row1 * 256 + col0);
        v11 = *(const float2*)(A + (size_t)row1 * 256 + col0 + 8);
    }
    uint4 o;
    o.x = packh2(v00.x, v00.y);   // a0: (r, c),(r, c+1)
    o.y = packh2(v10.x, v10.y);   // a1: (r+8, c)...
    o.z = packh2(v01.x, v01.y);   // a2: (r, c+8)...
    o.w = packh2(v11.x, v11.y);   // a3: (r+8, c+8)...
    Ap[t] = o;
}

// ===================== init h ===============================================
__global__ void init_h_kernel(const int* __restrict__ nodes,
                              const float* __restrict__ embed) {
    int idx = blockIdx.x * blockDim.x + threadIdx.x;
    if (idx >= NN * HH) return;
    int n = idx >> 8;
    int i = idx & 255;
    int tok = nodes[n];
    int pos = nodes[NN + n];
    int p = pos < 512 ? pos : 512;
    float pe = 0.0f;
    if (p > 0) {
        float posf = (float)(p - 1);
        float div = powf(10000.0f, (2.0f * (float)i) / 256.0f);
        float ang = posf / div;
        pe = (i & 1) ? cosf(ang) : sinf(ang);
    }
    d_h[idx] = embed[tok * HH + i] + pe;
}

// ===================== smem-free fp16 mma GEMM ==============================
// C[128x128 tile] = A[NN_PAD,256] @ B[256,Ntot] + bias
// A,B pre-permuted into m16n8k16 fragment layout. 8 warps: 4 m-rows x 2 n-cols,
// warp tile 32x64. Columns >= split go to C2.
__device__ __forceinline__ void mma16816(float* d, uint32_t a0, uint32_t a1,
                                         uint32_t a2, uint32_t a3,
                                         uint32_t b0, uint32_t b1) {
    asm volatile(
        "mma.sync.aligned.m16n8k16.row.col.f32.f16.f16.f32 "
        "{%0,%1,%2,%3}, {%4,%5,%6,%7}, {%8,%9}, {%0,%1,%2,%3};"
        : "+f"(d[0]), "+f"(d[1]), "+f"(d[2]), "+f"(d[3])
        : "r"(a0), "r"(a1), "r"(a2), "r"(a3), "r"(b0), "r"(b1));
}

__global__ __launch_bounds__(256, 2)
void gemm_h16(const uint4* __restrict__ Ap, const uint4* __restrict__ Bp,
              const float* __restrict__ bias,
              float* __restrict__ C1, int ldC1, int split,
              float* __restrict__ C2, int ldC2, int J2tot) {
    const int lane = threadIdx.x & 31;
    const int wid  = threadIdx.x >> 5;
    const int wr = wid & 3;          // warp row (32 rows each)
    const int wc = wid >> 2;         // warp col (64 cols each)
    const int mBase = blockIdx.x * 128;
    const int colBase = blockIdx.y * 128;
    const int i0 = blockIdx.x * 8 + wr * 2;
    const int j2base = blockIdx.y * 8 + wc * 4;

    float acc[2][8][4];
#pragma unroll
    for (int mi = 0; mi < 2; mi++)
#pragma unroll
        for (int j = 0; j < 8; j++)
#pragma unroll
            for (int r = 0; r < 4; r++) acc[mi][j][r] = 0.f;

#pragma unroll 4
    for (int kk = 0; kk < 16; kk++) {
        uint4 av0 = Ap[((size_t)(i0 * 16 + kk) * 32) + lane];
        uint4 av1 = Ap[((size_t)((i0 + 1) * 16 + kk) * 32) + lane];
        uint4 bq0 = Bp[((size_t)(kk * J2tot + j2base + 0) * 32) + lane];
        uint4 bq1 = Bp[((size_t)(kk * J2tot + j2base + 1) * 32) + lane];
        uint4 bq2 = Bp[((size_t)(kk * J2tot + j2base + 2) * 32) + lane];
        uint4 bq3 = Bp[((size_t)(kk * J2tot + j2base + 3) * 32) + lane];

        mma16816(acc[0][0], av0.x, av0.y, av0.z, av0.w, bq0.x, bq0.y);
        mma16816(acc[0][1], av0.x, av0.y, av0.z, av0.w, bq0.z, bq0.w);
        mma16816(acc[0][2], av0.x, av0.y, av0.z, av0.w, bq1.x, bq1.y);
        mma16816(acc[0][3], av0.x, av0.y, av0.z, av0.w, bq1.z, bq1.w);
        mma16816(acc[0][4], av0.x, av0.y, av0.z, av0.w, bq2.x, bq2.y);
        mma16816(acc[0][5], av0.x, av0.y, av0.z, av0.w, bq2.z, bq2.w);
        mma16816(acc[0][6], av0.x, av0.y, av0.z, av0.w, bq3.x, bq3.y);
        mma16816(acc[0][7], av0.x, av0.y, av0.z, av0.w, bq3.z, bq3.w);
        mma16816(acc[1][0], av1.x, av1.y, av1.z, av1.w, bq0.x, bq0.y);
        mma16816(acc[1][1], av1.x, av1.y, av1.z, av1.w, bq0.z, bq0.w);
        mma16816(acc[1][2], av1.x, av1.y, av1.z, av1.w, bq1.x, bq1.y);
        mma16816(acc[1][3], av1.x, av1.y, av1.z, av1.w, bq1.z, bq1.w);
        mma16816(acc[1][4], av1.x, av1.y, av1.z, av1.w, bq2.x, bq2.y);
        mma16816(acc[1][5], av1.x, av1.y, av1.z, av1.w, bq2.z, bq2.w);
        mma16816(acc[1][6], av1.x, av1.y, av1.z, av1.w, bq3.x, bq3.y);
        mma16816(acc[1][7], av1.x, av1.y, av1.z, av1.w, bq3.z, bq3.w);
    }

    // epilogue
#pragma unroll
    for (int mi = 0; mi < 2; mi++) {
        int row = mBase + wr * 32 + mi * 16 + (lane >> 2);
#pragma unroll
        for (int j = 0; j < 8; j++) {
            int col = colBase + wc * 64 + j * 8 + (lane & 3) * 2;
            float bx = bias[col], by = bias[col + 1];
            float* Cout;
            int ld, cc;
            if (col < split) { Cout = C1; ld = ldC1; cc = col; }
            else             { Cout = C2; ld = ldC2; cc = col - split; }
            float2 lo = make_float2(acc[mi][j][0] + bx, acc[mi][j][1] + by);
            float2 hi = make_float2(acc[mi][j][2] + bx, acc[mi][j][3] + by);
            *(float2*)(Cout + (size_t)row * ld + cc) = lo;
            *(float2*)(Cout + (size_t)(row + 8) * ld + cc) = hi;
        }
    }
}

// ===================== zero / scatter / gru ================================
__global__ void zero_kernel(float* __restrict__ p, int n4) {
    int i = blockIdx.x * blockDim.x + threadIdx.x;
    if (i < n4) ((float4*)p)[i] = make_float4(0.f, 0.f, 0.f, 0.f);
}

__global__ void scatter_kernel(const int* __restrict__ edges) {
    int idx = blockIdx.x * blockDim.x + threadIdx.x;
    int e = idx >> 6;
    if (e >= NE) return;
    int lane = idx & 63;
    int et  = edges[e * 3 + 0];
    int src = edges[e * 3 + 1];
    int tgt = edges[e * 3 + 2];
    const float4 v =
        *(const float4*)&d_trans[((size_t)src * 4 + et) * HH + lane * 4];
    float* dst = &d_msgs[(size_t)tgt * HH + lane * 4];
    asm volatile("red.global.add.v4.f32 [%0], {%1,%2,%3,%4};"
                 :: "l"(dst), "f"(v.x), "f"(v.y), "f"(v.z), "f"(v.w)
                 : "memory");
}

__device__ __forceinline__ float sigm(float x) { return 1.0f / (1.0f + expf(-x)); }

__global__ void gru_kernel() {
    int idx = blockIdx.x * blockDim.x + threadIdx.x;
    if (idx >= NN * 64) return;
    int n = idx >> 6;
    int c = (idx & 63) * 4;
    size_t b = (size_t)n * 768;
    float4 xz = *(float4*)&d_g1[b + c];
    float4 xr = *(float4*)&d_g1[b + 256 + c];
    float4 xh = *(float4*)&d_g1[b + 512 + c];
    float4 hz = *(float4*)&d_g2[b + c];
    float4 hr = *(float4*)&d_g2[b + 256 + c];
    float4 hh = *(float4*)&d_g2[b + 512 + c];
    float4 ho = *(float4*)&d_h[(size_t)n * 256 + c];
    float4 o;
#define GRU1(comp)                                                     \
    {                                                                  \
        float z = sigm(xz.comp + hz.comp);                             \
        float r = sigm(xr.comp + hr.comp);                             \
        float cand = tanhf(xh.comp + r * hh.comp);                     \
        o.comp = z * ho.comp + (1.0f - z) * cand;                      \
    }
    GRU1(x) GRU1(y) GRU1(z) GRU1(w)
#undef GRU1
    *(float4*)&d_h[(size_t)n * 256 + c] = o;
}

// ===================== readout ==============================================
__global__ void head_kernel(const float* __restrict__ gateW,
                            const float* __restrict__ gateb,
                            const float* __restrict__ outW,
                            const float* __restrict__ outb) {
    int gidx = blockIdx.x * blockDim.x + threadIdx.x;
    int warp = gidx >> 5;
    int lane = gidx & 31;
    if (warp >= NN) return;
    float g = 0.f, o0 = 0.f, o1 = 0.f;
    for (int c = lane; c < HH; c += 32) {
        float hv = d_h[(size_t)warp * HH + c];
        g  += hv * gateW[c];
        o0 += hv * outW[c * 2 + 0];
        o1 += hv * outW[c * 2 + 1];
    }
#pragma unroll
    for (int off = 16; off; off >>= 1) {
        g  += __shfl_down_sync(0xffffffffu, g,  off);
        o0 += __shfl_down_sync(0xffffffffu, o0, off);
        o1 += __shfl_down_sync(0xffffffffu, o1, off);
    }
    if (lane == 0) {
        d_gate[warp] = g + gateb[0];
        d_out2[warp * 2 + 0] = o0 + outb[0];
        d_out2[warp * 2 + 1] = o1 + outb[1];
    }
}

__global__ void max1_kernel() {
    __shared__ float s[256];
    float m = -INFINITY;
    for (int i = blockIdx.x * 256 + threadIdx.x; i < NN; i += gridDim.x * 256)
        m = fmaxf(m, d_gate[i]);
    s[threadIdx.x] = m;
    __syncthreads();
    for (int o = 128; o; o >>= 1) {
        if (threadIdx.x < o) s[threadIdx.x] = fmaxf(s[threadIdx.x], s[threadIdx.x + o]);
        __syncthreads();
    }
    if (threadIdx.x == 0) d_partial[blockIdx.x] = s[0];
}

__global__ void max2_kernel(int nb) {
    __shared__ float s[256];
    float m = (threadIdx.x < nb) ? d_partial[threadIdx.x] : -INFINITY;
    s[threadIdx.x] = m;
    __syncthreads();
    for (int o = 128; o; o >>= 1) {
        if (threadIdx.x < o) s[threadIdx.x] = fmaxf(s[threadIdx.x], s[threadIdx.x + o]);
        __syncthreads();
    }
    if (threadIdx.x == 0) d_gmax = s[0];
}

__global__ void cum_kernel(const int* __restrict__ gs) {
    if (threadIdx.x == 0 && blockIdx.x == 0) {
        int c = 0;
        d_cum[0] = 0;
        for (int i = 0; i < GG; i++) { c += gs[i]; d_cum[i + 1] = c; }
    }
}

__global__ void zero_sp_kernel() {
    int i = threadIdx.x;
    if (i < GG) d_S[i] = 0.f;
    if (i < GG * 2) d_P[i] = 0.f;
}

__global__ void accum_kernel() {
    int n = blockIdx.x * blockDim.x + threadIdx.x;
    if (n >= NN) return;
    int lo = 0, hi = GG;
    while (hi - lo > 1) {
        int mid = (lo + hi) >> 1;
        if (d_cum[mid] <= n) lo = mid; else hi = mid;
    }
    int seg = lo;
    float e = expf(d_gate[n] - d_gmax);
    atomicAdd(&d_S[seg], e);
    atomicAdd(&d_P[seg * 2 + 0], e * d_out2[n * 2 + 0]);
    atomicAdd(&d_P[seg * 2 + 1], e * d_out2[n * 2 + 1]);
}

__global__ void final_kernel(float* __restrict__ out) {
    int i = threadIdx.x;
    if (i < GG * 2) out[i] = d_P[i] / (d_S[i >> 1] + 1e-16f);
}

// ===================== host orchestration ===================================
extern "C" void kernel_launch(void* const* d_in, const int* in_sizes, int n_in,
                              void* d_out, int out_size) {
    const int*   nodes       = (const int*)d_in[0];
    const int*   graph_sizes = (const int*)d_in[1];
    const int*   edges       = (const int*)d_in[2];
    const float* embed       = (const float*)d_in[3];
    const float* tw          = (const float*)d_in[4];
    const float* tb          = (const float*)d_in[5];
    const float* gruW        = (const float*)d_in[6];
    const float* gruU        = (const float*)d_in[7];
    const float* gbi         = (const float*)d_in[8];
    const float* gbr         = (const float*)d_in[9];
    const float* gateW       = (const float*)d_in[10];
    const float* gateb       = (const float*)d_in[11];
    const float* outW        = (const float*)d_in[12];
    const float* outb        = (const float*)d_in[13];
    float* out = (float*)d_out;

    float *p_h, *p_trans, *p_msgs, *p_g1, *p_g2, *p_biasH;
    uint4 *p_hp, *p_msgsp, *p_BH, *p_BM;
    cudaGetSymbolAddress((void**)&p_h, d_h);
    cudaGetSymbolAddress((void**)&p_trans, d_trans);
    cudaGetSymbolAddress((void**)&p_msgs, d_msgs);
    cudaGetSymbolAddress((void**)&p_g1, d_g1);
    cudaGetSymbolAddress((void**)&p_g2, d_g2);
    cudaGetSymbolAddress((void**)&p_biasH, d_biasH);
    cudaGetSymbolAddress((void**)&p_hp, d_hp);
    cudaGetSymbolAddress((void**)&p_msgsp, d_msgsp);
    cudaGetSymbolAddress((void**)&p_BH, d_BH);
    cudaGetSymbolAddress((void**)&p_BM, d_BM);

    prep_BH_kernel<<<(2 * 16 * J2H * 32 + 255) / 256, 256>>>(tw, gruU);
    prep_BM_kernel<<<(2 * 16 * J2M * 32 + 255) / 256, 256>>>(gruW);
    prep_biasH_kernel<<<(2 * 1792 + 255) / 256, 256>>>(tb, gbr);
    init_h_kernel<<<(NN * HH + 255) / 256, 256>>>(nodes, embed);

    const int layers[4] = {0, 0, 0, 1};
    const int gridM = NN_PAD / 128;           // 782
    const int permBlocks = (MT16 * 512 + 255) / 256;

    for (int s = 0; s < 4; s++) {
        int l = layers[s];
        permute_a_kernel<<<permBlocks, 256>>>(p_h, p_hp);
        // fused: h @ [typeW(1024) | gruU(768)] -> trans + g2
        gemm_h16<<<dim3(gridM, 14), 256>>>(
            p_hp, p_BH + (size_t)l * 16 * J2H * 32, p_biasH + l * 1792,
            p_trans, 1024, 1024, p_g2, 768, J2H);
        zero_kernel<<<(NN * HH / 4 + 255) / 256, 256>>>(p_msgs, NN * HH / 4);
        scatter_kernel<<<(size_t)NE * 64 / 256, 256>>>(edges);
        permute_a_kernel<<<permBlocks, 256>>>(p_msgs, p_msgsp);
        gemm_h16<<<dim3(gridM, 6), 256>>>(
            p_msgsp, p_BM + (size_t)l * 16 * J2M * 32, gbi + l * 768,
            p_g1, 768, 1 << 28, p_g1, 768, J2M);
        gru_kernel<<<(NN * 64 + 255) / 256, 256>>>();
    }

    head_kernel<<<(NN * 32 + 255) / 256, 256>>>(gateW, gateb, outW, outb);
    max1_kernel<<<256, 256>>>();
    max2_kernel<<<1, 256>>>(256);
    cum_kernel<<<1, 1>>>(graph_sizes);
    zero_sp_kernel<<<1, 256>>>();
    accum_kernel<<<(NN + 255) / 256, 256>>>();
    final_kernel<<<1, 256>>>(out);
}

// round 5
// speedup vs baseline: 3.0563x; 1.0991x over previous
#include <cuda_runtime.h>
#include <cuda_fp16.h>
#include <cstdint>
#include <math.h>

#define NN 100000
#define NN_PAD 100096
#define MT16 (NN_PAD / 16)        // 6256 m16 tiles
#define GG 100
#define NE 1000000
#define HH 256
#define TT 4
#define J2H 112                   // 1792/16 n8-tile-pairs for fused h GEMM
#define J2M 48                    // 768/16 for msgs GEMM

// ===================== scratch (device globals) =============================
__device__ float  d_h[(size_t)NN * HH];
__device__ __half d_trans[(size_t)NN_PAD * TT * HH];  // [node][t][256] fp16
__device__ float  d_msgs[(size_t)NN * HH];
__device__ float  d_g1[(size_t)NN_PAD * 3 * HH];
__device__ float  d_g2[(size_t)NN_PAD * 3 * HH];
__device__ uint4  d_hp[(size_t)MT16 * 512];           // permuted fp16 A (h)
__device__ uint4  d_msgsp[(size_t)MT16 * 512];        // permuted fp16 A (msgs)
__device__ uint4  d_BH[(size_t)2 * 16 * J2H * 32];    // permuted fp16 B (tw|U)
__device__ uint4  d_BM[(size_t)2 * 16 * J2M * 32];    // permuted fp16 B (W)
__device__ float  d_biasH[2 * 1792];
__device__ float  d_pe[513 * 256];
__device__ float  d_gate[NN];
__device__ float  d_out2[NN * 2];
__device__ float  d_partial[256];
__device__ float  d_gmax;
__device__ int    d_cum[GG + 1];
__device__ float  d_S[GG];
__device__ float  d_P[GG * 2];

__device__ __forceinline__ uint32_t packh2(float lo, float hi) {
    __half2 h = __floats2half2_rn(lo, hi);
    return *reinterpret_cast<uint32_t*>(&h);
}

// write 4 consecutive h values (node n, cols c..c+3) into fragment layout
__device__ __forceinline__ void store_hp(int n, int c, float v0, float v1,
                                         float v2, float v3) {
    int i = n >> 4, r = n & 15, kk = c >> 4, cl = c & 15;
    uint32_t comp = ((cl >= 8) ? 8u : 0u) + ((r >= 8) ? 4u : 0u);
    int lane0 = (r & 7) * 4 + ((cl & 7) >> 1);
    char* base = (char*)d_hp + (((size_t)i * 512 + (size_t)kk * 32) * 16) + comp;
    *(__half2*)(base + (size_t)lane0 * 16)       = __floats2half2_rn(v0, v1);
    *(__half2*)(base + (size_t)(lane0 + 1) * 16) = __floats2half2_rn(v2, v3);
}

// ===================== weight prep: fragment-layout fp16 ====================
__device__ __forceinline__ float bvalH(const float* tw, const float* U,
                                       int l, int k, int n) {
    if (n < 1024) return tw[((size_t)(l * 4 + (n >> 8)) * 256 + k) * 256 + (n & 255)];
    return U[((size_t)l * 256 + k) * 768 + (n - 1024)];
}

__global__ void prep_BH_kernel(const float* __restrict__ tw,
                               const float* __restrict__ U) {
    int t = blockIdx.x * blockDim.x + threadIdx.x;
    if (t >= 2 * 16 * J2H * 32) return;
    int lane = t & 31;
    int t2 = t >> 5;
    int j2 = t2 % J2H;
    int t3 = t2 / J2H;
    int kk = t3 & 15;
    int l  = t3 >> 4;
    int g = lane >> 2, tt = lane & 3;
    int k0 = kk * 16 + tt * 2;
    uint4 o;
    {
        int n = (j2 * 2 + 0) * 8 + g;
        o.x = packh2(bvalH(tw, U, l, k0, n),     bvalH(tw, U, l, k0 + 1, n));
        o.y = packh2(bvalH(tw, U, l, k0 + 8, n), bvalH(tw, U, l, k0 + 9, n));
    }
    {
        int n = (j2 * 2 + 1) * 8 + g;
        o.z = packh2(bvalH(tw, U, l, k0, n),     bvalH(tw, U, l, k0 + 1, n));
        o.w = packh2(bvalH(tw, U, l, k0 + 8, n), bvalH(tw, U, l, k0 + 9, n));
    }
    d_BH[t] = o;
}

__global__ void prep_BM_kernel(const float* __restrict__ W) {
    int t = blockIdx.x * blockDim.x + threadIdx.x;
    if (t >= 2 * 16 * J2M * 32) return;
    int lane = t & 31;
    int t2 = t >> 5;
    int j2 = t2 % J2M;
    int t3 = t2 / J2M;
    int kk = t3 & 15;
    int l  = t3 >> 4;
    int g = lane >> 2, tt = lane & 3;
    int k0 = kk * 16 + tt * 2;
    const float* Wl = W + (size_t)l * 256 * 768;
    uint4 o;
    {
        int n = (j2 * 2 + 0) * 8 + g;
        o.x = packh2(Wl[(size_t)k0 * 768 + n],       Wl[(size_t)(k0 + 1) * 768 + n]);
        o.y = packh2(Wl[(size_t)(k0 + 8) * 768 + n], Wl[(size_t)(k0 + 9) * 768 + n]);
    }
    {
        int n = (j2 * 2 + 1) * 8 + g;
        o.z = packh2(Wl[(size_t)k0 * 768 + n],       Wl[(size_t)(k0 + 1) * 768 + n]);
        o.w = packh2(Wl[(size_t)(k0 + 8) * 768 + n], Wl[(size_t)(k0 + 9) * 768 + n]);
    }
    d_BM[t] = o;
}

__global__ void prep_biasH_kernel(const float* __restrict__ tb,
                                  const float* __restrict__ gbr) {
    int t = blockIdx.x * blockDim.x + threadIdx.x;
    if (t >= 2 * 1792) return;
    int l = t / 1792, n = t % 1792;
    d_biasH[t] = (n < 1024) ? tb[l * 1024 + n] : gbr[l * 768 + (n - 1024)];
}

// ===================== positional-encoding table ============================
__global__ void prep_pe_kernel() {
    int idx = blockIdx.x * blockDim.x + threadIdx.x;
    if (idx >= 513 * 256) return;
    int p = idx >> 8, i = idx & 255;
    float v = 0.0f;
    if (p > 0) {
        float div = powf(10000.0f, (2.0f * (float)i) / 256.0f);
        float ang = (float)(p - 1) / div;
        v = (i & 1) ? cosf(ang) : sinf(ang);
    }
    d_pe[idx] = v;
}

// ===================== init: h = embed + pe, also fragment layout ===========
__global__ void init_h_kernel(const int* __restrict__ nodes,
                              const float* __restrict__ embed) {
    int idx = blockIdx.x * blockDim.x + threadIdx.x;
    if (idx >= NN * 64) return;
    int n = idx >> 6;
    int c = (idx & 63) * 4;
    int tok = nodes[n];
    int pos = nodes[NN + n];
    int p = pos < 512 ? pos : 512;
    float4 e = *(const float4*)(embed + (size_t)tok * 256 + c);
    float4 pe = *(const float4*)(d_pe + (size_t)p * 256 + c);
    float4 o = make_float4(e.x + pe.x, e.y + pe.y, e.z + pe.z, e.w + pe.w);
    *(float4*)&d_h[(size_t)n * 256 + c] = o;
    store_hp(n, c, o.x, o.y, o.z, o.w);
}

// ===================== activation permute (msgs only) =======================
__global__ void permute_a_kernel(const float* __restrict__ A,
                                 uint4* __restrict__ Ap) {
    int t = blockIdx.x * blockDim.x + threadIdx.x;
    if (t >= MT16 * 512) return;
    int lane = t & 31;
    int kk = (t >> 5) & 15;
    int i  = t >> 9;
    int r = lane >> 2, c2 = (lane & 3) * 2;
    int row0 = i * 16 + r, row1 = row0 + 8;
    int col0 = kk * 16 + c2;
    float2 v00 = make_float2(0.f, 0.f), v01 = v00, v10 = v00, v11 = v00;
    if (row0 < NN) {
        v00 = *(const float2*)(A + (size_t)row0 * 256 + col0);
        v01 = *(const float2*)(A + (size_t)row0 * 256 + col0 + 8);
    }
    if (row1 < NN) {
        v10 = *(const float2*)(A + (size_t)row1 * 256 + col0);
        v11 = *(const float2*)(A + (size_t)row1 * 256 + col0 + 8);
    }
    uint4 o;
    o.x = packh2(v00.x, v00.y);
    o.y = packh2(v10.x, v10.y);
    o.z = packh2(v01.x, v01.y);
    o.w = packh2(v11.x, v11.y);
    Ap[t] = o;
}

// ===================== smem-free fp16 mma GEMM ==============================
__device__ __forceinline__ void mma16816(float* d, uint32_t a0, uint32_t a1,
                                         uint32_t a2, uint32_t a3,
                                         uint32_t b0, uint32_t b1) {
    asm volatile(
        "mma.sync.aligned.m16n8k16.row.col.f32.f16.f16.f32 "
        "{%0,%1,%2,%3}, {%4,%5,%6,%7}, {%8,%9}, {%0,%1,%2,%3};"
        : "+f"(d[0]), "+f"(d[1]), "+f"(d[2]), "+f"(d[3])
        : "r"(a0), "r"(a1), "r"(a2), "r"(a3), "r"(b0), "r"(b1));
}

// HALF1: C1 is __half* (trans); else C1 is float*
template <bool HALF1>
__global__ __launch_bounds__(256, 2)
void gemm_h16(const uint4* __restrict__ Ap, const uint4* __restrict__ Bp,
              const float* __restrict__ bias,
              void* __restrict__ C1v, int ldC1, int split,
              float* __restrict__ C2, int ldC2, int J2tot) {
    const int lane = threadIdx.x & 31;
    const int wid  = threadIdx.x >> 5;
    const int wr = wid & 3;
    const int wc = wid >> 2;
    const int mBase = blockIdx.x * 128;
    const int colBase = blockIdx.y * 128;
    const int i0 = blockIdx.x * 8 + wr * 2;
    const int j2base = blockIdx.y * 8 + wc * 4;

    float acc[2][8][4];
#pragma unroll
    for (int mi = 0; mi < 2; mi++)
#pragma unroll
        for (int j = 0; j < 8; j++)
#pragma unroll
            for (int r = 0; r < 4; r++) acc[mi][j][r] = 0.f;

#pragma unroll 4
    for (int kk = 0; kk < 16; kk++) {
        uint4 av0 = Ap[((size_t)(i0 * 16 + kk) * 32) + lane];
        uint4 av1 = Ap[((size_t)((i0 + 1) * 16 + kk) * 32) + lane];
        uint4 bq0 = Bp[((size_t)(kk * J2tot + j2base + 0) * 32) + lane];
        uint4 bq1 = Bp[((size_t)(kk * J2tot + j2base + 1) * 32) + lane];
        uint4 bq2 = Bp[((size_t)(kk * J2tot + j2base + 2) * 32) + lane];
        uint4 bq3 = Bp[((size_t)(kk * J2tot + j2base + 3) * 32) + lane];

        mma16816(acc[0][0], av0.x, av0.y, av0.z, av0.w, bq0.x, bq0.y);
        mma16816(acc[0][1], av0.x, av0.y, av0.z, av0.w, bq0.z, bq0.w);
        mma16816(acc[0][2], av0.x, av0.y, av0.z, av0.w, bq1.x, bq1.y);
        mma16816(acc[0][3], av0.x, av0.y, av0.z, av0.w, bq1.z, bq1.w);
        mma16816(acc[0][4], av0.x, av0.y, av0.z, av0.w, bq2.x, bq2.y);
        mma16816(acc[0][5], av0.x, av0.y, av0.z, av0.w, bq2.z, bq2.w);
        mma16816(acc[0][6], av0.x, av0.y, av0.z, av0.w, bq3.x, bq3.y);
        mma16816(acc[0][7], av0.x, av0.y, av0.z, av0.w, bq3.z, bq3.w);
        mma16816(acc[1][0], av1.x, av1.y, av1.z, av1.w, bq0.x, bq0.y);
        mma16816(acc[1][1], av1.x, av1.y, av1.z, av1.w, bq0.z, bq0.w);
        mma16816(acc[1][2], av1.x, av1.y, av1.z, av1.w, bq1.x, bq1.y);
        mma16816(acc[1][3], av1.x, av1.y, av1.z, av1.w, bq1.z, bq1.w);
        mma16816(acc[1][4], av1.x, av1.y, av1.z, av1.w, bq2.x, bq2.y);
        mma16816(acc[1][5], av1.x, av1.y, av1.z, av1.w, bq2.z, bq2.w);
        mma16816(acc[1][6], av1.x, av1.y, av1.z, av1.w, bq3.x, bq3.y);
        mma16816(acc[1][7], av1.x, av1.y, av1.z, av1.w, bq3.z, bq3.w);
    }

#pragma unroll
    for (int mi = 0; mi < 2; mi++) {
        int row = mBase + wr * 32 + mi * 16 + (lane >> 2);
#pragma unroll
        for (int j = 0; j < 8; j++) {
            int col = colBase + wc * 64 + j * 8 + (lane & 3) * 2;
            float bx = bias[col], by = bias[col + 1];
            float a0 = acc[mi][j][0] + bx, a1 = acc[mi][j][1] + by;
            float a2 = acc[mi][j][2] + bx, a3 = acc[mi][j][3] + by;
            if (col < split) {
                if (HALF1) {
                    __half* C1 = (__half*)C1v;
                    *(__half2*)(C1 + (size_t)row * ldC1 + col) =
                        __floats2half2_rn(a0, a1);
                    *(__half2*)(C1 + (size_t)(row + 8) * ldC1 + col) =
                        __floats2half2_rn(a2, a3);
                } else {
                    float* C1 = (float*)C1v;
                    *(float2*)(C1 + (size_t)row * ldC1 + col) = make_float2(a0, a1);
                    *(float2*)(C1 + (size_t)(row + 8) * ldC1 + col) = make_float2(a2, a3);
                }
            } else {
                int cc = col - split;
                *(float2*)(C2 + (size_t)row * ldC2 + cc) = make_float2(a0, a1);
                *(float2*)(C2 + (size_t)(row + 8) * ldC2 + cc) = make_float2(a2, a3);
            }
        }
    }
}

// ===================== zero / scatter / gru ================================
__global__ void zero_kernel(float* __restrict__ p, int n4) {
    int i = blockIdx.x * blockDim.x + threadIdx.x;
    if (i < n4) ((float4*)p)[i] = make_float4(0.f, 0.f, 0.f, 0.f);
}

__global__ void scatter_kernel(const int* __restrict__ edges) {
    int idx = blockIdx.x * blockDim.x + threadIdx.x;
    int e = idx >> 5;
    if (e >= NE) return;
    int lane = idx & 31;
    int et  = edges[e * 3 + 0];
    int src = edges[e * 3 + 1];
    int tgt = edges[e * 3 + 2];
    const uint4 v = *(const uint4*)&d_trans[((size_t)src * 4 + et) * HH + lane * 8];
    float2 fa = __half22float2(*(const __half2*)&v.x);
    float2 fb = __half22float2(*(const __half2*)&v.y);
    float2 fc = __half22float2(*(const __half2*)&v.z);
    float2 fd = __half22float2(*(const __half2*)&v.w);
    float* dst = &d_msgs[(size_t)tgt * HH + lane * 8];
    asm volatile("red.global.add.v4.f32 [%0], {%1,%2,%3,%4};"
                 :: "l"(dst), "f"(fa.x), "f"(fa.y), "f"(fb.x), "f"(fb.y)
                 : "memory");
    asm volatile("red.global.add.v4.f32 [%0], {%1,%2,%3,%4};"
                 :: "l"(dst + 4), "f"(fc.x), "f"(fc.y), "f"(fd.x), "f"(fd.y)
                 : "memory");
}

__device__ __forceinline__ float sigm(float x) { return 1.0f / (1.0f + expf(-x)); }

__global__ void gru_kernel() {
    int idx = blockIdx.x * blockDim.x + threadIdx.x;
    if (idx >= NN * 64) return;
    int n = idx >> 6;
    int c = (idx & 63) * 4;
    size_t b = (size_t)n * 768;
    float4 xz = *(float4*)&d_g1[b + c];
    float4 xr = *(float4*)&d_g1[b + 256 + c];
    float4 xh = *(float4*)&d_g1[b + 512 + c];
    float4 hz = *(float4*)&d_g2[b + c];
    float4 hr = *(float4*)&d_g2[b + 256 + c];
    float4 hh = *(float4*)&d_g2[b + 512 + c];
    float4 ho = *(float4*)&d_h[(size_t)n * 256 + c];
    float4 o;
#define GRU1(comp)                                                     \
    {                                                                  \
        float z = sigm(xz.comp + hz.comp);                             \
        float r = sigm(xr.comp + hr.comp);                             \
        float cand = tanhf(xh.comp + r * hh.comp);                     \
        o.comp = z * ho.comp + (1.0f - z) * cand;                      \
    }
    GRU1(x) GRU1(y) GRU1(z) GRU1(w)
#undef GRU1
    *(float4*)&d_h[(size_t)n * 256 + c] = o;
    store_hp(n, c, o.x, o.y, o.z, o.w);
}

// ===================== readout ==============================================
__global__ void head_kernel(const float* __restrict__ gateW,
                            const float* __restrict__ gateb,
                            const float* __restrict__ outW,
                            const float* __restrict__ outb) {
    int gidx = blockIdx.x * blockDim.x + threadIdx.x;
    int warp = gidx >> 5;
    int lane = gidx & 31;
    if (warp >= NN) return;
    float g = 0.f, o0 = 0.f, o1 = 0.f;
    for (int c = lane; c < HH; c += 32) {
        float hv = d_h[(size_t)warp * HH + c];
        g  += hv * gateW[c];
        o0 += hv * outW[c * 2 + 0];
        o1 += hv * outW[c * 2 + 1];
    }
#pragma unroll
    for (int off = 16; off; off >>= 1) {
        g  += __shfl_down_sync(0xffffffffu, g,  off);
        o0 += __shfl_down_sync(0xffffffffu, o0, off);
        o1 += __shfl_down_sync(0xffffffffu, o1, off);
    }
    if (lane == 0) {
        d_gate[warp] = g + gateb[0];
        d_out2[warp * 2 + 0] = o0 + outb[0];
        d_out2[warp * 2 + 1] = o1 + outb[1];
    }
}

__global__ void max1_kernel() {
    __shared__ float s[256];
    float m = -INFINITY;
    for (int i = blockIdx.x * 256 + threadIdx.x; i < NN; i += gridDim.x * 256)
        m = fmaxf(m, d_gate[i]);
    s[threadIdx.x] = m;
    __syncthreads();
    for (int o = 128; o; o >>= 1) {
        if (threadIdx.x < o) s[threadIdx.x] = fmaxf(s[threadIdx.x], s[threadIdx.x + o]);
        __syncthreads();
    }
    if (threadIdx.x == 0) d_partial[blockIdx.x] = s[0];
}

__global__ void max2_kernel(int nb) {
    __shared__ float s[256];
    float m = (threadIdx.x < nb) ? d_partial[threadIdx.x] : -INFINITY;
    s[threadIdx.x] = m;
    __syncthreads();
    for (int o = 128; o; o >>= 1) {
        if (threadIdx.x < o) s[threadIdx.x] = fmaxf(s[threadIdx.x], s[threadIdx.x + o]);
        __syncthreads();
    }
    if (threadIdx.x == 0) d_gmax = s[0];
}

__global__ void cum_kernel(const int* __restrict__ gs) {
    if (threadIdx.x == 0 && blockIdx.x == 0) {
        int c = 0;
        d_cum[0] = 0;
        for (int i = 0; i < GG; i++) { c += gs[i]; d_cum[i + 1] = c; }
    }
}

__global__ void zero_sp_kernel() {
    int i = threadIdx.x;
    if (i < GG) d_S[i] = 0.f;
    if (i < GG * 2) d_P[i] = 0.f;
}

__global__ void accum_kernel() {
    int n = blockIdx.x * blockDim.x + threadIdx.x;
    if (n >= NN) return;
    int lo = 0, hi = GG;
    while (hi - lo > 1) {
        int mid = (lo + hi) >> 1;
        if (d_cum[mid] <= n) lo = mid; else hi = mid;
    }
    int seg = lo;
    float e = expf(d_gate[n] - d_gmax);
    atomicAdd(&d_S[seg], e);
    atomicAdd(&d_P[seg * 2 + 0], e * d_out2[n * 2 + 0]);
    atomicAdd(&d_P[seg * 2 + 1], e * d_out2[n * 2 + 1]);
}

__global__ void final_kernel(float* __restrict__ out) {
    int i = threadIdx.x;
    if (i < GG * 2) out[i] = d_P[i] / (d_S[i >> 1] + 1e-16f);
}

// ===================== host orchestration ===================================
extern "C" void kernel_launch(void* const* d_in, const int* in_sizes, int n_in,
                              void* d_out, int out_size) {
    const int*   nodes       = (const int*)d_in[0];
    const int*   graph_sizes = (const int*)d_in[1];
    const int*   edges       = (const int*)d_in[2];
    const float* embed       = (const float*)d_in[3];
    const float* tw          = (const float*)d_in[4];
    const float* tb          = (const float*)d_in[5];
    const float* gruW        = (const float*)d_in[6];
    const float* gruU        = (const float*)d_in[7];
    const float* gbi         = (const float*)d_in[8];
    const float* gbr         = (const float*)d_in[9];
    const float* gateW       = (const float*)d_in[10];
    const float* gateb       = (const float*)d_in[11];
    const float* outW        = (const float*)d_in[12];
    const float* outb        = (const float*)d_in[13];
    float* out = (float*)d_out;

    float *p_msgs, *p_g1, *p_g2, *p_biasH;
    __half* p_trans;
    uint4 *p_hp, *p_msgsp, *p_BH, *p_BM;
    cudaGetSymbolAddress((void**)&p_trans, d_trans);
    cudaGetSymbolAddress((void**)&p_msgs, d_msgs);
    cudaGetSymbolAddress((void**)&p_g1, d_g1);
    cudaGetSymbolAddress((void**)&p_g2, d_g2);
    cudaGetSymbolAddress((void**)&p_biasH, d_biasH);
    cudaGetSymbolAddress((void**)&p_hp, d_hp);
    cudaGetSymbolAddress((void**)&p_msgsp, d_msgsp);
    cudaGetSymbolAddress((void**)&p_BH, d_BH);
    cudaGetSymbolAddress((void**)&p_BM, d_BM);

    prep_pe_kernel<<<(513 * 256 + 255) / 256, 256>>>();
    prep_BH_kernel<<<(2 * 16 * J2H * 32 + 255) / 256, 256>>>(tw, gruU);
    prep_BM_kernel<<<(2 * 16 * J2M * 32 + 255) / 256, 256>>>(gruW);
    prep_biasH_kernel<<<(2 * 1792 + 255) / 256, 256>>>(tb, gbr);
    init_h_kernel<<<(NN * 64 + 255) / 256, 256>>>(nodes, embed);

    const int layers[4] = {0, 0, 0, 1};
    const int gridM = NN_PAD / 128;
    const int permBlocks = (MT16 * 512 + 255) / 256;

    for (int s = 0; s < 4; s++) {
        int l = layers[s];
        // fused: h @ [typeW(1024, ->fp16 trans) | gruU(768, ->fp32 g2)]
        gemm_h16<true><<<dim3(gridM, 14), 256>>>(
            p_hp, p_BH + (size_t)l * 16 * J2H * 32, p_biasH + l * 1792,
            p_trans, 1024, 1024, p_g2, 768, J2H);
        zero_kernel<<<(NN * HH / 4 + 255) / 256, 256>>>(p_msgs, NN * HH / 4);
        scatter_kernel<<<(size_t)NE * 32 / 256, 256>>>(edges);
        permute_a_kernel<<<permBlocks, 256>>>(p_msgs, p_msgsp);
        gemm_h16<false><<<dim3(gridM, 6), 256>>>(
            p_msgsp, p_BM + (size_t)l * 16 * J2M * 32, gbi + l * 768,
            p_g1, 768, 1 << 28, p_g1, 768, J2M);
        gru_kernel<<<(NN * 64 + 255) / 256, 256>>>();
    }

    head_kernel<<<(NN * 32 + 255) / 256, 256>>>(gateW, gateb, outW, outb);
    max1_kernel<<<256, 256>>>();
    max2_kernel<<<1, 256>>>(256);
    cum_kernel<<<1, 1>>>(graph_sizes);
    zero_sp_kernel<<<1, 256>>>();
    accum_kernel<<<(NN + 255) / 256, 256>>>();
    final_kernel<<<1, 256>>>(out);
}